// round 12
// baseline (speedup 1.0000x reference)
#include <cuda_runtime.h>
#include <cuda_fp16.h>
#include <math.h>
#include <stdint.h>

#define EPS 1e-5f

// ---------------- scratch (no allocations allowed; zero-initialized at load) ----------------
__device__ __half g_xp [16u * 66 * 66 * 256];  // x padded NHWC fp16 (borders stay zero)
__device__ __half g_xp2[16u * 66 * 66 * 64];   // ef1 padded NHWC fp16 (borders stay zero)
__device__ __half g_ef [16u * 64 * 64 * 64];   // ef NHWC fp16 [b][h*64+w][ch]
__device__ __half g_w1p[36 * 64 * 64];         // conv1 weights [kc=t*4+cq][oc][ch]
__device__ __half g_w2p[9 * 64 * 64];          // conv2 weights [t][oc][ch]
__device__ __half g_wop[256 * 64];             // out_w fp16 [oc][ch]
__device__ float  g_xph[16 * 64 * 256];        // per-(b,h) channel sums of x
__device__ float  g_ep1[16 * 32 * 64];         // partial e-pool sums [b][tile][ch]
__device__ float  g_gate[16 * 256];

__device__ __forceinline__ uint32_t smem_u32(const void* p) {
    uint32_t a;
    asm("{ .reg .u64 t; cvta.to.shared.u64 t, %1; cvt.u32.u64 %0, t; }" : "=r"(a) : "l"(p));
    return a;
}

// 16B-unit XOR swizzle inside a 128B row: row stride 128B, unit u in [0,8)
__device__ __forceinline__ uint32_t swz(uint32_t row, uint32_t u) {
    return row * 128u + ((u ^ (row & 7u)) * 16u);
}

#define CP_ASYNC16(dst, src) \
    asm volatile("cp.async.cg.shared.global [%0], [%1], 16;" :: "r"(dst), "l"(src))
#define CP_COMMIT() asm volatile("cp.async.commit_group;" ::: "memory")
#define CP_WAIT0()  asm volatile("cp.async.wait_group 0;" ::: "memory")

#define LDMATRIX_X4(r0, r1, r2, r3, addr) \
    asm volatile("ldmatrix.sync.aligned.m8n8.x4.shared.b16 {%0,%1,%2,%3}, [%4];" \
                 : "=r"(r0), "=r"(r1), "=r"(r2), "=r"(r3) : "r"(addr))

#define MMA_16816(c, a0, a1, a2, a3, b0, b1) \
    asm volatile("mma.sync.aligned.m16n8k16.row.col.f32.f16.f16.f32 " \
                 "{%0,%1,%2,%3}, {%4,%5,%6,%7}, {%8,%9}, {%0,%1,%2,%3};" \
                 : "+f"((c)[0]), "+f"((c)[1]), "+f"((c)[2]), "+f"((c)[3]) \
                 : "r"(a0), "r"(a1), "r"(a2), "r"(a3), "r"(b0), "r"(b1))

// ---------------- pre-pass: x (fp32 NCHW) -> padded NHWC fp16 + per-(b,h) channel sums ----------------
__global__ __launch_bounds__(256)
void convert_x(const float* __restrict__ x)
{
    const int h = blockIdx.x, b = blockIdx.y, tid = threadIdx.x;
    __shared__ float t[64][65];
    for (int c0 = 0; c0 < 256; c0 += 64) {
        __syncthreads();
        for (int i = tid; i < 4096; i += 256) {
            int c = i >> 6, w = i & 63;
            t[c][w] = x[(((size_t)b * 256 + c0 + c) * 64 + h) * 64 + w];
        }
        __syncthreads();
        for (int i = tid; i < 4096; i += 256) {
            int w = i >> 6, c = i & 63;
            g_xp[((b * 66u + h + 1) * 66u + (w + 1)) * 256 + c0 + c] = __float2half_rn(t[c][w]);
        }
        if (tid < 64) {   // per-channel row sum (fp32)
            float s = 0.f;
            #pragma unroll 8
            for (int w = 0; w < 64; ++w) s += t[tid][w];
            g_xph[(b * 64 + h) * 256 + c0 + tid] = s;
        }
    }
}

// ---------------- pre-pass: all weight reorders in one launch ----------------
__global__ __launch_bounds__(256)
void prep_all(const float* __restrict__ w1, const float* __restrict__ w2,
              const float* __restrict__ wo)
{
    int idx = blockIdx.x * 256 + threadIdx.x;
    if (idx < 36 * 64 * 64) {
        int j  = idx & 63;
        int oc = (idx >> 6) & 63;
        int kc = idx >> 12;
        int t = kc >> 2, cq = kc & 3;
        int ch = cq * 64 + j, dy = t / 3, dx = t % 3;
        g_w1p[idx] = __float2half_rn(w1[((oc * 256 + ch) * 3 + dy) * 3 + dx]);
        return;
    }
    idx -= 36 * 64 * 64;
    if (idx < 9 * 64 * 64) {
        int j  = idx & 63;
        int oc = (idx >> 6) & 63;
        int t  = idx >> 12;
        g_w2p[idx] = __float2half_rn(w2[(oc * 64 + j) * 9 + t]);
        return;
    }
    idx -= 9 * 64 * 64;
    if (idx < 256 * 64) g_wop[idx] = __float2half_rn(wo[idx]);
}

// ---------------- mma.sync conv3x3 + BN + ReLU ----------------
// CTA tile: M=128 (2 output rows x 64 w) x N=64 oc. 256 threads, 8 warps in 4(M) x 2(N) grid;
// each warp: 32 rows x 32 oc, acc[2][4][4] = 32 regs.
// A-tile (input) staged once per 64-ch group via cp.async; B (weights) double-buffered per tap.
// For !FIRST, also emits deterministic per-channel partial pool sums (g_ep1).
template<int CIN, int NG, bool FIRST>
__global__ __launch_bounds__(256)
void conv_mma(const float* __restrict__ bias,
              const float* __restrict__ bng, const float* __restrict__ bnb,
              const float* __restrict__ bnm, const float* __restrict__ bnv)
{
    extern __shared__ __align__(128) char dsm[];
    __half* sIn  = (__half*)dsm;                    // 264*128 = 33792 B
    char*   sBm  = dsm + 264 * 128;                 // 2 * 8192 B
    float*  sScale = (float*)(dsm + 264 * 128 + 16384);
    float*  sShift = sScale + 64;

    const int tid  = threadIdx.x;
    const int wid  = tid >> 5;
    const int lane = tid & 31;
    const int h0 = blockIdx.x * 2;
    const int b  = blockIdx.y;
    const int m0 = (wid & 3) * 32;      // M-slice
    const int n0 = (wid >> 2) * 32;     // N-slice

    const __half* __restrict__ xin = FIRST ? g_xp : g_xp2;
    const __half* __restrict__ wgt = FIRST ? g_w1p : g_w2p;

    if (tid < 64) {
        float inv = bng[tid] * rsqrtf(bnv[tid] + EPS);
        sScale[tid] = inv;
        sShift[tid] = bnb[tid] - bnm[tid] * inv + bias[tid] * inv;
    }

    const uint32_t sInb = smem_u32(sIn);
    const uint32_t sBb  = smem_u32(sBm);

    int rb[2];
    #pragma unroll
    for (int mt = 0; mt < 2; ++mt) {
        int m_r = m0 + mt * 16 + (lane & 15);
        rb[mt] = (m_r >> 6) * 66 + (m_r & 63);
    }
    const uint32_t u_hi  = (uint32_t)(lane >> 4);
    const uint32_t b_row = (uint32_t)(n0 + (lane & 15));

    float acc[2][4][4];
    #pragma unroll
    for (int mt = 0; mt < 2; ++mt)
        #pragma unroll
        for (int j = 0; j < 4; ++j)
            #pragma unroll
            for (int q = 0; q < 4; ++q) acc[mt][j][q] = 0.f;

    for (int g = 0; g < NG; ++g) {
        if (g) __syncthreads();   // prior group's smem reads done
        const int ch0 = g * 64;
        // stage input tile: 264 rows x 8 units (cp.async, 256 threads)
        for (int i = tid; i < 264 * 8; i += 256) {
            int r = i >> 3, u = i & 7;
            int dyr = r / 66, wpos = r - dyr * 66;
            const __half* src = xin + ((size_t)((b * 66 + h0 + dyr) * 66 + wpos)) * CIN + ch0 + u * 8;
            CP_ASYNC16(sInb + swz((uint32_t)r, (uint32_t)u), src);
        }
        // stage B for tap 0 (512 units / 256 threads)
        {
            const int kci = FIRST ? g : 0;
            const __half* ws = wgt + (size_t)kci * 4096;
            #pragma unroll
            for (int q = 0; q < 2; ++q) {
                int i = q * 256 + tid, r = i >> 3, u = i & 7;
                CP_ASYNC16(sBb + swz((uint32_t)r, (uint32_t)u), ws + r * 64 + u * 8);
            }
        }
        CP_COMMIT();
        CP_WAIT0();
        __syncthreads();

        for (int t = 0; t < 9; ++t) {
            if (t) { CP_WAIT0(); __syncthreads(); }
            if (t < 8) {   // prefetch next tap's B into the other buffer
                const int kci = FIRST ? ((t + 1) * 4 + g) : (t + 1);
                const __half* ws = wgt + (size_t)kci * 4096;
                const uint32_t dstb = sBb + (uint32_t)(((t + 1) & 1) * 8192);
                #pragma unroll
                for (int q = 0; q < 2; ++q) {
                    int i = q * 256 + tid, r = i >> 3, u = i & 7;
                    CP_ASYNC16(dstb + swz((uint32_t)r, (uint32_t)u), ws + r * 64 + u * 8);
                }
                CP_COMMIT();
            }
            const int off = (t / 3) * 66 + (t % 3);
            const uint32_t bbase = sBb + (uint32_t)((t & 1) * 8192);
            #pragma unroll
            for (int s = 0; s < 4; ++s) {
                const uint32_t u = (uint32_t)(s * 2) + u_hi;
                uint32_t a[2][4];
                #pragma unroll
                for (int mt = 0; mt < 2; ++mt)
                    LDMATRIX_X4(a[mt][0], a[mt][1], a[mt][2], a[mt][3],
                                sInb + swz((uint32_t)(rb[mt] + off), u));
                uint32_t bf[2][4];
                #pragma unroll
                for (int nt = 0; nt < 2; ++nt)
                    LDMATRIX_X4(bf[nt][0], bf[nt][1], bf[nt][2], bf[nt][3],
                                bbase + swz(b_row + nt * 16, u));
                #pragma unroll
                for (int mt = 0; mt < 2; ++mt)
                    #pragma unroll
                    for (int j = 0; j < 4; ++j) {
                        const int nt = j >> 1, lo = j & 1;
                        MMA_16816(acc[mt][j], a[mt][0], a[mt][1], a[mt][2], a[mt][3],
                                  bf[nt][lo], bf[nt][2 + lo]);
                    }
            }
        }
    }

    // ---------------- epilogue: BN + ReLU (+ pool partials for !FIRST) ----------------
    const int r0 = lane >> 2;
    const int c0 = (lane & 3) * 2;
    float ps[8];
    #pragma unroll
    for (int k = 0; k < 8; ++k) ps[k] = 0.f;

    #pragma unroll
    for (int mt = 0; mt < 2; ++mt) {
        #pragma unroll
        for (int half = 0; half < 2; ++half) {
            const int m = m0 + mt * 16 + r0 + half * 8;
            const int hh = m >> 6, w = m & 63;
            if (FIRST) {
                __half* dst = g_xp2 + ((size_t)((b * 66 + h0 + hh + 1) * 66) + (w + 1)) * 64;
                #pragma unroll
                for (int j = 0; j < 4; ++j) {
                    const int oc = n0 + j * 8 + c0;
                    float v0 = fmaxf(acc[mt][j][half * 2]     * sScale[oc]     + sShift[oc],     0.f);
                    float v1 = fmaxf(acc[mt][j][half * 2 + 1] * sScale[oc + 1] + sShift[oc + 1], 0.f);
                    *(half2*)(dst + oc) = __floats2half2_rn(v0, v1);
                }
            } else {
                __half* dst = g_ef + ((size_t)(b * 4096 + (h0 + hh) * 64 + w)) * 64;
                #pragma unroll
                for (int j = 0; j < 4; ++j) {
                    const int oc = n0 + j * 8 + c0;
                    float v0 = fmaxf(acc[mt][j][half * 2]     * sScale[oc]     + sShift[oc],     0.f);
                    float v1 = fmaxf(acc[mt][j][half * 2 + 1] * sScale[oc + 1] + sShift[oc + 1], 0.f);
                    half2 hv = __floats2half2_rn(v0, v1);
                    *(half2*)(dst + oc) = hv;
                    // pool accumulates the rounded fp16 values (matches g_ef contents)
                    float2 vr = __half22float2(hv);
                    ps[j * 2]     += vr.x;
                    ps[j * 2 + 1] += vr.y;
                }
            }
        }
    }

    if (!FIRST) {
        // deterministic reduce: shfl-xor over r0 (lanes sharing c0), then fold warps via smem
        #pragma unroll
        for (int k = 0; k < 8; ++k) {
            #pragma unroll
            for (int off = 4; off < 32; off <<= 1)
                ps[k] += __shfl_xor_sync(0xFFFFFFFFu, ps[k], off);
        }
        __syncthreads();                 // all smem (MMA) use done; reuse sIn area
        float* spool = (float*)dsm;      // [8][32]
        if (lane < 4) {
            #pragma unroll
            for (int j = 0; j < 4; ++j) {
                spool[wid * 32 + j * 8 + c0]     = ps[j * 2];
                spool[wid * 32 + j * 8 + c0 + 1] = ps[j * 2 + 1];
            }
        }
        __syncthreads();
        if (tid < 64) {
            float s;
            if (tid < 32)
                s = (spool[0 * 32 + tid] + spool[1 * 32 + tid])
                  + (spool[2 * 32 + tid] + spool[3 * 32 + tid]);
            else {
                const int c = tid - 32;
                s = (spool[4 * 32 + c] + spool[5 * 32 + c])
                  + (spool[6 * 32 + c] + spool[7 * 32 + c]);
            }
            g_ep1[(b * 32 + blockIdx.x) * 64 + tid] = s;
        }
    }
}

// ---------------- fused gate: pools fold -> MLP1+BN+ReLU -> MLP2+sigmoid ----------------
__global__ __launch_bounds__(256)
void gate_fused(const float* __restrict__ g1_w, const float* __restrict__ g1_b,
                const float* __restrict__ gbng, const float* __restrict__ gbnb,
                const float* __restrict__ gbnm, const float* __restrict__ gbnv,
                const float* __restrict__ g2_w, const float* __restrict__ g2_b)
{
    const int b = blockIdx.x, t = threadIdx.x;
    __shared__ float gv[320];
    __shared__ float hv[128];

    for (int i = t; i < 320; i += 256) {
        float s = 0.f;
        if (i < 256) {
            #pragma unroll 8
            for (int h = 0; h < 64; ++h) s += g_xph[(b * 64 + h) * 256 + i];
        } else {
            const int c = i - 256;
            #pragma unroll 8
            for (int seg = 0; seg < 32; ++seg) s += g_ep1[(b * 32 + seg) * 64 + c];
        }
        gv[i] = s * (1.f / 4096.f);
    }
    __syncthreads();

    if (t < 128) {
        float s = g1_b[t];
        const float* wrow = g1_w + t * 320;
        #pragma unroll 4
        for (int k = 0; k < 320; ++k) s = fmaf(gv[k], wrow[k], s);
        float inv = gbng[t] * rsqrtf(gbnv[t] + EPS);
        s = (s - gbnm[t]) * inv + gbnb[t];
        hv[t] = fmaxf(s, 0.f);
    }
    __syncthreads();

    float s = g2_b[t];
    const float* wrow = g2_w + t * 128;
    #pragma unroll 4
    for (int k = 0; k < 128; ++k) s = fmaf(hv[k], wrow[k], s);
    g_gate[b * 256 + t] = 1.f / (1.f + expf(-s));
}

// ---------------- 1x1 conv (64->256) via HMMA + gated residual add ----------------
__global__ __launch_bounds__(256)
void out_mma(const float* __restrict__ x, const float* __restrict__ out_b,
             float* __restrict__ out)
{
    __shared__ __align__(128) __half sW[256 * 64];
    __shared__ __align__(128) __half sE[64 * 64];
    const int tid = threadIdx.x, wid = tid >> 5, lane = tid & 31;
    const int h = blockIdx.x, b = blockIdx.y;

    for (int i = tid; i < 2048; i += 256) {
        int r = i >> 3, u = i & 7;
        *(uint4*)((char*)sW + swz((uint32_t)r, (uint32_t)u)) = *(const uint4*)(g_wop + r * 64 + u * 8);
    }
    for (int i = tid; i < 512; i += 256) {
        int r = i >> 3, u = i & 7;
        *(uint4*)((char*)sE + swz((uint32_t)r, (uint32_t)u)) =
            *(const uint4*)(g_ef + ((size_t)(b * 4096 + h * 64 + r)) * 64 + u * 8);
    }
    __syncthreads();

    const int m0 = wid * 32;
    const uint32_t sWb = smem_u32(sW), sEb = smem_u32(sE);
    const uint32_t a_row = (uint32_t)(m0 + (lane & 15));
    const uint32_t b_row = (uint32_t)(lane & 15);
    const uint32_t u_hi  = (uint32_t)(lane >> 4);

    float acc[2][8][4];
    #pragma unroll
    for (int mt = 0; mt < 2; ++mt)
        #pragma unroll
        for (int j = 0; j < 8; ++j)
            #pragma unroll
            for (int q = 0; q < 4; ++q) acc[mt][j][q] = 0.f;

    #pragma unroll
    for (int s = 0; s < 4; ++s) {
        const uint32_t u = (uint32_t)(s * 2) + u_hi;
        uint32_t a[2][4];
        #pragma unroll
        for (int mt = 0; mt < 2; ++mt)
            LDMATRIX_X4(a[mt][0], a[mt][1], a[mt][2], a[mt][3], sWb + swz(a_row + mt * 16, u));
        uint32_t bf[4][4];
        #pragma unroll
        for (int nt = 0; nt < 4; ++nt)
            LDMATRIX_X4(bf[nt][0], bf[nt][1], bf[nt][2], bf[nt][3], sEb + swz(b_row + nt * 16, u));
        #pragma unroll
        for (int mt = 0; mt < 2; ++mt)
            #pragma unroll
            for (int j = 0; j < 8; ++j) {
                const int nt = j >> 1, lo = j & 1;
                MMA_16816(acc[mt][j], a[mt][0], a[mt][1], a[mt][2], a[mt][3],
                          bf[nt][lo], bf[nt][2 + lo]);
            }
    }

    const int r0 = lane >> 2, c0 = (lane & 3) * 2;
    #pragma unroll
    for (int mt = 0; mt < 2; ++mt) {
        #pragma unroll
        for (int half = 0; half < 2; ++half) {
            const int oc = m0 + mt * 16 + r0 + half * 8;
            const float gt = g_gate[b * 256 + oc];
            const float bia = out_b[oc];
            const size_t base = ((size_t)(b * 256 + oc) * 64 + h) * 64;
            #pragma unroll
            for (int j = 0; j < 8; ++j) {
                const int w = j * 8 + c0;
                float2 xv = *(const float2*)&x[base + w];
                float2 o;
                o.x = xv.x + gt * (acc[mt][j][half * 2]     + bia);
                o.y = xv.y + gt * (acc[mt][j][half * 2 + 1] + bia);
                *(float2*)&out[base + w] = o;
            }
        }
    }
}

// ---------------- launch ----------------
extern "C" void kernel_launch(void* const* d_in, const int* in_sizes, int n_in,
                              void* d_out, int out_size)
{
    const float* x     = (const float*)d_in[0];
    const float* ec1_w = (const float*)d_in[1];
    const float* ec1_b = (const float*)d_in[2];
    const float* bn1_g = (const float*)d_in[3];
    const float* bn1_b = (const float*)d_in[4];
    const float* bn1_m = (const float*)d_in[5];
    const float* bn1_v = (const float*)d_in[6];
    const float* ec2_w = (const float*)d_in[7];
    const float* ec2_b = (const float*)d_in[8];
    const float* bn2_g = (const float*)d_in[9];
    const float* bn2_b = (const float*)d_in[10];
    const float* bn2_m = (const float*)d_in[11];
    const float* bn2_v = (const float*)d_in[12];
    const float* g1_w  = (const float*)d_in[13];
    const float* g1_b  = (const float*)d_in[14];
    const float* gbn_g = (const float*)d_in[15];
    const float* gbn_b = (const float*)d_in[16];
    const float* gbn_m = (const float*)d_in[17];
    const float* gbn_v = (const float*)d_in[18];
    const float* g2_w  = (const float*)d_in[19];
    const float* g2_b  = (const float*)d_in[20];
    const float* out_w = (const float*)d_in[21];
    const float* out_b = (const float*)d_in[22];
    float* out = (float*)d_out;

    const int CONV_SMEM = 264 * 128 + 2 * 8192 + 2 * 64 * (int)sizeof(float);  // 50688
    cudaFuncSetAttribute(conv_mma<256, 4, true >, cudaFuncAttributeMaxDynamicSharedMemorySize, CONV_SMEM);
    cudaFuncSetAttribute(conv_mma< 64, 1, false>, cudaFuncAttributeMaxDynamicSharedMemorySize, CONV_SMEM);

    convert_x<<<dim3(64, 16), 256>>>(x);
    prep_all<<<784, 256>>>(ec1_w, ec2_w, out_w);

    conv_mma<256, 4, true ><<<dim3(32, 16), 256, CONV_SMEM>>>(ec1_b, bn1_g, bn1_b, bn1_m, bn1_v);
    conv_mma< 64, 1, false><<<dim3(32, 16), 256, CONV_SMEM>>>(ec2_b, bn2_g, bn2_b, bn2_m, bn2_v);

    gate_fused<<<16, 256>>>(g1_w, g1_b, gbn_g, gbn_b, gbn_m, gbn_v, g2_w, g2_b);
    out_mma<<<dim3(64, 16), 256>>>(x, out_b, out);
}